// round 9
// baseline (speedup 1.0000x reference)
#include <cuda_runtime.h>
#include <cuda_bf16.h>
#include <cstdint>

#define NN 100000
#define EE 1600000
#define D  128
#define CAP 128

// ---------------- device scratch (no allocations allowed) ----------------
__device__ int      g_cnt[NN];
__device__ int      g_colp[(size_t)NN * CAP];
__device__ float    g_acc[(size_t)NN * D];   // self-GEMM partial (fp32)
__device__ uint16_t g_Xh[(size_t)NN * D];    // bf16 bits, hi part of x
__device__ uint16_t g_Xl[(size_t)NN * D];
__device__ uint16_t g_hh[(size_t)NN * D];    // hidden layer hi/lo
__device__ uint16_t g_hl[(size_t)NN * D];
__device__ uint16_t g_mh[(size_t)NN * D];    // mean hi/lo
__device__ uint16_t g_ml[(size_t)NN * D];
// W transposed+split: [j=0..127][k=0..255] bf16, k<128 -> Wself[k][j], k>=128 -> Wneigh[k-128][j]
__device__ uint16_t g_WT1h[128 * 256];
__device__ uint16_t g_WT1l[128 * 256];
__device__ uint16_t g_WT2h[128 * 256];
__device__ uint16_t g_WT2l[128 * 256];

__device__ __forceinline__ uint16_t bf_hi(float v) {
    return __bfloat16_as_ushort(__float2bfloat16(v));
}
__device__ __forceinline__ float bf_f(uint16_t u) {
    return __uint_as_float((uint32_t)u << 16);
}

// ---------------- fused init: zero counters + weight prep + X split ----------------
__global__ void init_kernel(const float* __restrict__ x,
                            const float* __restrict__ W1s, const float* __restrict__ W1n,
                            const float* __restrict__ W2s, const float* __restrict__ W2n) {
    int idx = blockIdx.x * blockDim.x + threadIdx.x;
    if (idx < NN) g_cnt[idx] = 0;
    if (idx < 2 * 128 * 256) {
        int layer = idx >> 15;
        int e = idx & 32767;
        int j = e >> 8;
        int k = e & 255;
        const float* Ws = layer ? W2s : W1s;
        const float* Wn = layer ? W2n : W1n;
        float v = (k < 128) ? Ws[k * 128 + j] : Wn[(k - 128) * 128 + j];
        uint16_t hi = bf_hi(v);
        uint16_t lo = bf_hi(v - bf_f(hi));
        if (layer) { g_WT2h[e] = hi; g_WT2l[e] = lo; }
        else       { g_WT1h[e] = hi; g_WT1l[e] = lo; }
    }
    if (idx < NN * D / 4) {
        float4 v = ((const float4*)x)[idx];
        uint16_t h0 = bf_hi(v.x), h1 = bf_hi(v.y), h2 = bf_hi(v.z), h3 = bf_hi(v.w);
        uint16_t l0 = bf_hi(v.x - bf_f(h0)), l1 = bf_hi(v.y - bf_f(h1));
        uint16_t l2 = bf_hi(v.z - bf_f(h2)), l3 = bf_hi(v.w - bf_f(h3));
        uint2 hw, lw;
        hw.x = (uint32_t)h0 | ((uint32_t)h1 << 16);
        hw.y = (uint32_t)h2 | ((uint32_t)h3 << 16);
        lw.x = (uint32_t)l0 | ((uint32_t)l1 << 16);
        lw.y = (uint32_t)l2 | ((uint32_t)l3 << 16);
        *(uint2*)(g_Xh + (size_t)idx * 4) = hw;
        *(uint2*)(g_Xl + (size_t)idx * 4) = lw;
    }
}

// ---------------- bucket fill: one atomic per edge, no scan ----------------
__global__ void fill_kernel(const int* __restrict__ src, const int* __restrict__ dst) {
    int e = blockIdx.x * blockDim.x + threadIdx.x;
    if (e < EE) {
        int d = dst[e];
        int pos = atomicAdd(&g_cnt[d], 1);
        if (pos < CAP) g_colp[(size_t)d * CAP + pos] = src[e];
    }
}

// ---------------- aggregation helpers ----------------
__device__ __forceinline__ void write_mean(int w, int lane, float4 acc, int cnt) {
    float inv = (cnt > 0) ? 1.0f / (float)cnt : 0.0f;
    acc.x *= inv; acc.y *= inv; acc.z *= inv; acc.w *= inv;
    uint16_t h0 = bf_hi(acc.x), h1 = bf_hi(acc.y), h2 = bf_hi(acc.z), h3 = bf_hi(acc.w);
    uint16_t l0 = bf_hi(acc.x - bf_f(h0)), l1 = bf_hi(acc.y - bf_f(h1));
    uint16_t l2 = bf_hi(acc.z - bf_f(h2)), l3 = bf_hi(acc.w - bf_f(h3));
    uint2 hw, lw;
    hw.x = (uint32_t)h0 | ((uint32_t)h1 << 16);
    hw.y = (uint32_t)h2 | ((uint32_t)h3 << 16);
    lw.x = (uint32_t)l0 | ((uint32_t)l1 << 16);
    lw.y = (uint32_t)l2 | ((uint32_t)l3 << 16);
    *(uint2*)(g_mh + (size_t)w * D + lane * 4) = hw;
    *(uint2*)(g_ml + (size_t)w * D + lane * 4) = lw;
}

__device__ __forceinline__ void agg_node_f32(const float* __restrict__ x, int w, int lane) {
    int cnt = min(g_cnt[w], CAP);
    const int* cp = g_colp + (size_t)w * CAP;
    const float4* x4 = (const float4*)x;
    float4 acc = make_float4(0.f, 0.f, 0.f, 0.f);
    for (int e = 0; e < cnt; e++) {
        int s = cp[e];
        float4 v = x4[(size_t)s * 32 + lane];
        acc.x += v.x; acc.y += v.y; acc.z += v.z; acc.w += v.w;
    }
    write_mean(w, lane, acc, cnt);
}

__device__ __forceinline__ void agg_node_bf(int w, int lane) {
    int cnt = min(g_cnt[w], CAP);
    const int* cp = g_colp + (size_t)w * CAP;
    float4 acc = make_float4(0.f, 0.f, 0.f, 0.f);
    for (int e = 0; e < cnt; e++) {
        int s = cp[e];
        uint2 hv = *(const uint2*)(g_hh + (size_t)s * D + lane * 4);
        uint2 lv = *(const uint2*)(g_hl + (size_t)s * D + lane * 4);
        acc.x += bf_f((uint16_t)(hv.x & 0xFFFF)) + bf_f((uint16_t)(lv.x & 0xFFFF));
        acc.y += bf_f((uint16_t)(hv.x >> 16))    + bf_f((uint16_t)(lv.x >> 16));
        acc.z += bf_f((uint16_t)(hv.y & 0xFFFF)) + bf_f((uint16_t)(lv.y & 0xFFFF));
        acc.w += bf_f((uint16_t)(hv.y >> 16))    + bf_f((uint16_t)(lv.y >> 16));
    }
    write_mean(w, lane, acc, cnt);
}

// ---------------- GEMM body: C(128x128) = A(hi/lo bf16) @ WT[:, kbase:kbase+128], 3-term ----------------
// 256 threads, 8 warps (4m x 2n), warp tile 32x64, K=128 in 2 chunks of 64, single-buffer cp.async.
// EPI 0: store fp32 partial to g_acc.  EPI 1: += g_acc + bias, ReLU, split-bf16 store to g_hh/g_hl.
// EPI 2: += g_acc + bias, fp32 store to outF.
#define PITCHB 144                         // bytes per smem row (72 bf16)
#define MATB   (128 * PITCHB)              // 18432 bytes per matrix tile
#define SM_BYTES (4 * MATB)                // 73728: Ah, Al, Bh, Bl (single stage)

__device__ __forceinline__ void mma_bf16(float* c, const uint32_t* a, uint32_t b0, uint32_t b1) {
    asm volatile("mma.sync.aligned.m16n8k16.row.col.f32.bf16.bf16.f32 "
                 "{%0,%1,%2,%3}, {%4,%5,%6,%7}, {%8,%9}, {%0,%1,%2,%3};"
                 : "+f"(c[0]), "+f"(c[1]), "+f"(c[2]), "+f"(c[3])
                 : "r"(a[0]), "r"(a[1]), "r"(a[2]), "r"(a[3]), "r"(b0), "r"(b1));
}
__device__ __forceinline__ void ldsm_x4(uint32_t* r, uint32_t addr) {
    asm volatile("ldmatrix.sync.aligned.m8n8.x4.shared.b16 {%0,%1,%2,%3}, [%4];"
                 : "=r"(r[0]), "=r"(r[1]), "=r"(r[2]), "=r"(r[3]) : "r"(addr));
}
__device__ __forceinline__ void cp16(uint32_t dst, const void* src, uint32_t sz) {
    asm volatile("cp.async.cg.shared.global [%0], [%1], 16, %2;" :: "r"(dst), "l"(src), "r"(sz));
}
__device__ __forceinline__ uint32_t smem_u32(const void* p) {
    uint32_t a;
    asm("{ .reg .u64 t; cvta.to.shared.u64 t, %1; cvt.u32.u64 %0, t; }" : "=r"(a) : "l"(p));
    return a;
}

template <int EPI>
__device__ __forceinline__ void gemm_body(
        const uint16_t* __restrict__ Ah_g, const uint16_t* __restrict__ Al_g,
        const uint16_t* __restrict__ WTh, const uint16_t* __restrict__ WTl,
        int kbase, const float* __restrict__ bias, float* __restrict__ outF,
        int row0, char* smemraw) {
    const uint32_t sbase = smem_u32(smemraw);
    const int tid  = threadIdx.x;
    const int wid  = tid >> 5;
    const int lane = tid & 31;
    const int grp  = lane >> 2;
    const int qp   = lane & 3;
    const int wm   = wid >> 1;    // 0..3 -> rows wm*32
    const int wn   = wid & 1;     // 0..1 -> cols wn*64

    const uint32_t arow_off = (uint32_t)((lane & 15) * PITCHB + ((lane >> 4) << 4));
    const uint32_t brow_off = (uint32_t)((((lane >> 4) << 3) + (lane & 7)) * PITCHB + (((lane >> 3) & 1) << 4));

    float acc[2][8][4];
#pragma unroll
    for (int mf = 0; mf < 2; mf++)
#pragma unroll
        for (int nf = 0; nf < 8; nf++)
#pragma unroll
            for (int q = 0; q < 4; q++) acc[mf][nf][q] = 0.f;

#pragma unroll
    for (int chunk = 0; chunk < 2; chunk++) {
        const int kc = chunk * 64;           // A column base
        const int k0 = kbase + chunk * 64;   // WT column base
        // stage A (hi+lo): 2048 x 16B, 8 per thread
#pragma unroll
        for (int i = 0; i < 8; i++) {
            int idx = tid + i * 256;
            int mat = idx >> 10;
            int e   = idx & 1023;
            int r   = e >> 3;
            int c16 = e & 7;
            int gr  = row0 + r;
            int grs = (gr < NN) ? gr : 0;
            const uint16_t* srcp = (mat ? Al_g : Ah_g) + (size_t)grs * D + kc + c16 * 8;
            uint32_t dst = sbase + (mat ? MATB : 0) + r * PITCHB + c16 * 16;
            cp16(dst, srcp, (gr < NN) ? 16u : 0u);
        }
        // stage B (hi+lo): 2048 x 16B, 8 per thread
#pragma unroll
        for (int i = 0; i < 8; i++) {
            int idx = tid + i * 256;
            int mat = idx >> 10;
            int e   = idx & 1023;
            int j   = e >> 3;
            int c16 = e & 7;
            const uint16_t* srcp = (mat ? WTl : WTh) + (size_t)j * 256 + k0 + c16 * 8;
            uint32_t dst = sbase + (mat ? 3 * MATB : 2 * MATB) + j * PITCHB + c16 * 16;
            cp16(dst, srcp, 16u);
        }
        asm volatile("cp.async.commit_group;" ::: "memory");
        asm volatile("cp.async.wait_group 0;" ::: "memory");
        __syncthreads();

        const uint32_t aBaseH = sbase + (wm * 32) * PITCHB + arow_off;
        const uint32_t aBaseL = aBaseH + MATB;
        const uint32_t bBaseH = sbase + 2 * MATB + (wn * 64) * PITCHB + brow_off;
        const uint32_t bBaseL = bBaseH + MATB;

#pragma unroll
        for (int ks = 0; ks < 64; ks += 16) {
            uint32_t ah[2][4], al[2][4];
#pragma unroll
            for (int mf = 0; mf < 2; mf++) {
                ldsm_x4(ah[mf], aBaseH + mf * (16 * PITCHB) + ks * 2);
                ldsm_x4(al[mf], aBaseL + mf * (16 * PITCHB) + ks * 2);
            }
#pragma unroll
            for (int np = 0; np < 4; np++) {
                uint32_t bh[4], bl[4];
                ldsm_x4(bh, bBaseH + np * (16 * PITCHB) + ks * 2);
                ldsm_x4(bl, bBaseL + np * (16 * PITCHB) + ks * 2);
                int nf0 = np * 2, nf1 = np * 2 + 1;
                mma_bf16(acc[0][nf0], ah[0], bh[0], bh[1]);
                mma_bf16(acc[1][nf0], ah[1], bh[0], bh[1]);
                mma_bf16(acc[0][nf1], ah[0], bh[2], bh[3]);
                mma_bf16(acc[1][nf1], ah[1], bh[2], bh[3]);
                mma_bf16(acc[0][nf0], al[0], bh[0], bh[1]);
                mma_bf16(acc[1][nf0], al[1], bh[0], bh[1]);
                mma_bf16(acc[0][nf1], al[0], bh[2], bh[3]);
                mma_bf16(acc[1][nf1], al[1], bh[2], bh[3]);
                mma_bf16(acc[0][nf0], ah[0], bl[0], bl[1]);
                mma_bf16(acc[1][nf0], ah[1], bl[0], bl[1]);
                mma_bf16(acc[0][nf1], ah[0], bl[2], bl[3]);
                mma_bf16(acc[1][nf1], ah[1], bl[2], bl[3]);
            }
        }
        __syncthreads();
    }

    // epilogue
#pragma unroll
    for (int mf = 0; mf < 2; mf++) {
#pragma unroll
        for (int nf = 0; nf < 8; nf++) {
            int c = wn * 64 + nf * 8 + qp * 2;
            int r = row0 + wm * 32 + mf * 16 + grp;
#pragma unroll
            for (int half = 0; half < 2; half++) {
                int rr = r + half * 8;
                if (rr >= NN) continue;
                float v0 = acc[mf][nf][half * 2 + 0];
                float v1 = acc[mf][nf][half * 2 + 1];
                if (EPI == 0) {
                    *(float2*)(g_acc + (size_t)rr * D + c) = make_float2(v0, v1);
                } else {
                    float2 p = *(const float2*)(g_acc + (size_t)rr * D + c);
                    v0 += p.x + bias[c];
                    v1 += p.y + bias[c + 1];
                    if (EPI == 1) {
                        v0 = fmaxf(v0, 0.f); v1 = fmaxf(v1, 0.f);
                        uint16_t h0 = bf_hi(v0), h1 = bf_hi(v1);
                        uint16_t l0 = bf_hi(v0 - bf_f(h0)), l1 = bf_hi(v1 - bf_f(h1));
                        *(uint32_t*)(g_hh + (size_t)rr * D + c) = (uint32_t)h0 | ((uint32_t)h1 << 16);
                        *(uint32_t*)(g_hl + (size_t)rr * D + c) = (uint32_t)l0 | ((uint32_t)l1 << 16);
                    } else {
                        *(float2*)(outF + (size_t)rr * D + c) = make_float2(v0, v1);
                    }
                }
            }
        }
    }
}

// ---------------- fused kernel: self-GEMM CTAs interleaved with aggregation CTAs ----------------
// grid = 13282: bids < 1564 alternate gemm(even)/agg(odd); bids >= 1564 all agg.
// gemm CTAs: 782 (one 128-row tile each). agg CTAs: 12500 (8 nodes each).
template <bool L2>
__global__ void __launch_bounds__(256, 2)
fused_kernel(const float* __restrict__ x,
             const uint16_t* __restrict__ Ah_g, const uint16_t* __restrict__ Al_g,
             const uint16_t* __restrict__ WTh, const uint16_t* __restrict__ WTl) {
    extern __shared__ char smm[];
    int bid = blockIdx.x;
    bool isG = (bid < 1564) && ((bid & 1) == 0);
    if (isG) {
        int gi = bid >> 1;
        gemm_body<0>(Ah_g, Al_g, WTh, WTl, 0, nullptr, nullptr, gi * 128, smm);
    } else {
        int ai = (bid < 1564) ? (bid >> 1) : (bid - 782);
        int wid  = threadIdx.x >> 5;
        int lane = threadIdx.x & 31;
        int w = ai * 8 + wid;
        if (w < NN) {
            if (L2) agg_node_bf(w, lane);
            else    agg_node_f32(x, w, lane);
        }
    }
}

// ---------------- neigh GEMM kernel: mean @ Wn + g_acc (+bias, epilogue per EPI) ----------------
template <int EPI>
__global__ void __launch_bounds__(256, 2)
neigh_kernel(const uint16_t* __restrict__ WTh, const uint16_t* __restrict__ WTl,
             const float* __restrict__ bias, float* __restrict__ outF) {
    extern __shared__ char smm[];
    gemm_body<EPI>(g_mh, g_ml, WTh, WTl, 128, bias, outF, blockIdx.x * 128, smm);
}

// ---------------- launch ----------------
extern "C" void kernel_launch(void* const* d_in, const int* in_sizes, int n_in,
                              void* d_out, int out_size) {
    const float* x   = (const float*)d_in[0];
    const float* W1s = (const float*)d_in[1];
    const float* W1n = (const float*)d_in[2];
    const float* b1  = (const float*)d_in[3];
    const float* W2s = (const float*)d_in[4];
    const float* W2n = (const float*)d_in[5];
    const float* b2  = (const float*)d_in[6];
    const int*   src = (const int*)d_in[7];
    const int*   dst = (const int*)d_in[8];
    float* out = (float*)d_out;

    uint16_t *xh, *xl, *hh, *hl, *wt1h, *wt1l, *wt2h, *wt2l;
    cudaGetSymbolAddress((void**)&xh, g_Xh);
    cudaGetSymbolAddress((void**)&xl, g_Xl);
    cudaGetSymbolAddress((void**)&hh, g_hh);
    cudaGetSymbolAddress((void**)&hl, g_hl);
    cudaGetSymbolAddress((void**)&wt1h, g_WT1h);
    cudaGetSymbolAddress((void**)&wt1l, g_WT1l);
    cudaGetSymbolAddress((void**)&wt2h, g_WT2h);
    cudaGetSymbolAddress((void**)&wt2l, g_WT2l);

    cudaFuncSetAttribute(fused_kernel<false>, cudaFuncAttributeMaxDynamicSharedMemorySize, SM_BYTES);
    cudaFuncSetAttribute(fused_kernel<true>,  cudaFuncAttributeMaxDynamicSharedMemorySize, SM_BYTES);
    cudaFuncSetAttribute(neigh_kernel<1>,     cudaFuncAttributeMaxDynamicSharedMemorySize, SM_BYTES);
    cudaFuncSetAttribute(neigh_kernel<2>,     cudaFuncAttributeMaxDynamicSharedMemorySize, SM_BYTES);

    const int fusedGrid = 13282;   // 782 gemm + 12500 agg

    init_kernel<<<(NN * D / 4 + 255) / 256, 256>>>(x, W1s, W1n, W2s, W2n);
    fill_kernel<<<(EE + 255) / 256, 256>>>(src, dst);

    // layer 1: [self-GEMM || agg], then neigh-GEMM (+acc, +bias, relu, split)
    fused_kernel<false><<<fusedGrid, 256, SM_BYTES>>>(x, xh, xl, wt1h, wt1l);
    neigh_kernel<1><<<782, 256, SM_BYTES>>>(wt1h, wt1l, b1, nullptr);

    // layer 2: [self-GEMM || agg], then neigh-GEMM (+acc, +bias) -> out
    fused_kernel<true><<<fusedGrid, 256, SM_BYTES>>>(x, hh, hl, wt2h, wt2l);
    neigh_kernel<2><<<782, 256, SM_BYTES>>>(wt2h, wt2l, b2, out);
}

// round 10
// speedup vs baseline: 1.8562x; 1.8562x over previous
#include <cuda_runtime.h>
#include <cuda_bf16.h>
#include <cstdint>

#define NN 100000
#define EE 1600000
#define D  128
#define CAP 128

// ---------------- device scratch (no allocations allowed) ----------------
__device__ int      g_cnt[NN];
__device__ int      g_colp[(size_t)NN * CAP];
__device__ uint16_t g_Xh[(size_t)NN * D];   // bf16 bits, hi part of x
__device__ uint16_t g_Xl[(size_t)NN * D];
__device__ uint16_t g_hh[(size_t)NN * D];   // hidden layer hi/lo
__device__ uint16_t g_hl[(size_t)NN * D];
__device__ uint16_t g_mh[(size_t)NN * D];   // mean hi/lo
__device__ uint16_t g_ml[(size_t)NN * D];
// W transposed+split: [j=0..127][k=0..255] bf16, k<128 -> Wself[k][j], k>=128 -> Wneigh[k-128][j]
__device__ uint16_t g_WT1h[128 * 256];
__device__ uint16_t g_WT1l[128 * 256];
__device__ uint16_t g_WT2h[128 * 256];
__device__ uint16_t g_WT2l[128 * 256];

__device__ __forceinline__ uint16_t bf_hi(float v) {
    return __bfloat16_as_ushort(__float2bfloat16(v));
}
__device__ __forceinline__ float bf_f(uint16_t u) {
    return __uint_as_float((uint32_t)u << 16);
}

// ---------------- fused init: zero counters + weight prep + X split ----------------
__global__ void init_kernel(const float* __restrict__ x,
                            const float* __restrict__ W1s, const float* __restrict__ W1n,
                            const float* __restrict__ W2s, const float* __restrict__ W2n) {
    int idx = blockIdx.x * blockDim.x + threadIdx.x;
    if (idx < NN) g_cnt[idx] = 0;
    if (idx < 2 * 128 * 256) {
        int layer = idx >> 15;
        int e = idx & 32767;
        int j = e >> 8;
        int k = e & 255;
        const float* Ws = layer ? W2s : W1s;
        const float* Wn = layer ? W2n : W1n;
        float v = (k < 128) ? Ws[k * 128 + j] : Wn[(k - 128) * 128 + j];
        uint16_t hi = bf_hi(v);
        uint16_t lo = bf_hi(v - bf_f(hi));
        if (layer) { g_WT2h[e] = hi; g_WT2l[e] = lo; }
        else       { g_WT1h[e] = hi; g_WT1l[e] = lo; }
    }
    if (idx < NN * D / 4) {
        float4 v = ((const float4*)x)[idx];
        uint16_t h0 = bf_hi(v.x), h1 = bf_hi(v.y), h2 = bf_hi(v.z), h3 = bf_hi(v.w);
        uint16_t l0 = bf_hi(v.x - bf_f(h0)), l1 = bf_hi(v.y - bf_f(h1));
        uint16_t l2 = bf_hi(v.z - bf_f(h2)), l3 = bf_hi(v.w - bf_f(h3));
        uint2 hw, lw;
        hw.x = (uint32_t)h0 | ((uint32_t)h1 << 16);
        hw.y = (uint32_t)h2 | ((uint32_t)h3 << 16);
        lw.x = (uint32_t)l0 | ((uint32_t)l1 << 16);
        lw.y = (uint32_t)l2 | ((uint32_t)l3 << 16);
        *(uint2*)(g_Xh + (size_t)idx * 4) = hw;
        *(uint2*)(g_Xl + (size_t)idx * 4) = lw;
    }
}

// ---------------- bucket fill: one atomic per edge, no scan ----------------
__global__ void fill_kernel(const int* __restrict__ src, const int* __restrict__ dst) {
    int e = blockIdx.x * blockDim.x + threadIdx.x;
    if (e < EE) {
        int d = dst[e];
        int pos = atomicAdd(&g_cnt[d], 1);
        if (pos < CAP) g_colp[(size_t)d * CAP + pos] = src[e];
    }
}

// ---------------- aggregation: warp per dst node, bf16 hi/lo out ----------------
__device__ __forceinline__ void write_mean(int w, int lane, float4 acc, int cnt) {
    float inv = (cnt > 0) ? 1.0f / (float)cnt : 0.0f;
    acc.x *= inv; acc.y *= inv; acc.z *= inv; acc.w *= inv;
    uint16_t h0 = bf_hi(acc.x), h1 = bf_hi(acc.y), h2 = bf_hi(acc.z), h3 = bf_hi(acc.w);
    uint16_t l0 = bf_hi(acc.x - bf_f(h0)), l1 = bf_hi(acc.y - bf_f(h1));
    uint16_t l2 = bf_hi(acc.z - bf_f(h2)), l3 = bf_hi(acc.w - bf_f(h3));
    uint2 hw, lw;
    hw.x = (uint32_t)h0 | ((uint32_t)h1 << 16);
    hw.y = (uint32_t)h2 | ((uint32_t)h3 << 16);
    lw.x = (uint32_t)l0 | ((uint32_t)l1 << 16);
    lw.y = (uint32_t)l2 | ((uint32_t)l3 << 16);
    *(uint2*)(g_mh + (size_t)w * D + lane * 4) = hw;
    *(uint2*)(g_ml + (size_t)w * D + lane * 4) = lw;
}

__global__ void agg_f32_kernel(const float* __restrict__ x) {
    int gt   = blockIdx.x * blockDim.x + threadIdx.x;
    int w    = gt >> 5;
    int lane = gt & 31;
    if (w >= NN) return;
    int cnt = min(g_cnt[w], CAP);
    const int* cp = g_colp + (size_t)w * CAP;
    const float4* x4 = (const float4*)x;
    float4 acc = make_float4(0.f, 0.f, 0.f, 0.f);
    for (int e = 0; e < cnt; e++) {
        int s = cp[e];
        float4 v = x4[(size_t)s * 32 + lane];
        acc.x += v.x; acc.y += v.y; acc.z += v.z; acc.w += v.w;
    }
    write_mean(w, lane, acc, cnt);
}

__global__ void agg_bf_kernel() {
    int gt   = blockIdx.x * blockDim.x + threadIdx.x;
    int w    = gt >> 5;
    int lane = gt & 31;
    if (w >= NN) return;
    int cnt = min(g_cnt[w], CAP);
    const int* cp = g_colp + (size_t)w * CAP;
    float4 acc = make_float4(0.f, 0.f, 0.f, 0.f);
    for (int e = 0; e < cnt; e++) {
        int s = cp[e];
        uint2 hv = *(const uint2*)(g_hh + (size_t)s * D + lane * 4);
        uint2 lv = *(const uint2*)(g_hl + (size_t)s * D + lane * 4);
        acc.x += bf_f((uint16_t)(hv.x & 0xFFFF)) + bf_f((uint16_t)(lv.x & 0xFFFF));
        acc.y += bf_f((uint16_t)(hv.x >> 16))    + bf_f((uint16_t)(lv.x >> 16));
        acc.z += bf_f((uint16_t)(hv.y & 0xFFFF)) + bf_f((uint16_t)(lv.y & 0xFFFF));
        acc.w += bf_f((uint16_t)(hv.y >> 16))    + bf_f((uint16_t)(lv.y >> 16));
    }
    write_mean(w, lane, acc, cnt);
}

// ---------------- async-pipelined HMMA GEMM (R6 base + term-major HMMA order) ----------------
// CTA 128x128, 256 threads, 8 warps (4m x 2n), warp tile 32x64, K=256 in 4 chunks of 64,
// double-buffered cp.async. Per k-step: load ALL frags, then 3 passes of 16 HMMAs
// (AhBh, AlBh, AhBl) -> same-accumulator reuse distance 16.
#define PITCHB 144                         // bytes per smem row (72 bf16)
#define MATB   (128 * PITCHB)              // 18432 bytes per matrix tile
#define STAGEB (4 * MATB)                  // 73728 bytes per stage
#define SM_BYTES (2 * STAGEB)              // 147456

__device__ __forceinline__ void mma_bf16(float* c, const uint32_t* a, uint32_t b0, uint32_t b1) {
    asm volatile("mma.sync.aligned.m16n8k16.row.col.f32.bf16.bf16.f32 "
                 "{%0,%1,%2,%3}, {%4,%5,%6,%7}, {%8,%9}, {%0,%1,%2,%3};"
                 : "+f"(c[0]), "+f"(c[1]), "+f"(c[2]), "+f"(c[3])
                 : "r"(a[0]), "r"(a[1]), "r"(a[2]), "r"(a[3]), "r"(b0), "r"(b1));
}
__device__ __forceinline__ void ldsm_x4(uint32_t* r, uint32_t addr) {
    asm volatile("ldmatrix.sync.aligned.m8n8.x4.shared.b16 {%0,%1,%2,%3}, [%4];"
                 : "=r"(r[0]), "=r"(r[1]), "=r"(r[2]), "=r"(r[3]) : "r"(addr));
}
__device__ __forceinline__ void cp16(uint32_t dst, const void* src, uint32_t sz) {
    asm volatile("cp.async.cg.shared.global [%0], [%1], 16, %2;" :: "r"(dst), "l"(src), "r"(sz));
}
__device__ __forceinline__ uint32_t smem_u32(const void* p) {
    uint32_t a;
    asm("{ .reg .u64 t; cvta.to.shared.u64 t, %1; cvt.u32.u64 %0, t; }" : "=r"(a) : "l"(p));
    return a;
}

template <bool RELU, bool SPLIT>
__global__ void __launch_bounds__(256, 1)
gemm_async_kernel(const uint16_t* __restrict__ Sh, const uint16_t* __restrict__ Sl,
                  const uint16_t* __restrict__ WTh, const uint16_t* __restrict__ WTl,
                  const float* __restrict__ bias,
                  float* __restrict__ outF, uint16_t* __restrict__ outH, uint16_t* __restrict__ outL) {
    extern __shared__ char sm[];
    const uint32_t sbase = smem_u32(sm);
    const int tid  = threadIdx.x;
    const int wid  = tid >> 5;
    const int lane = tid & 31;
    const int grp  = lane >> 2;
    const int qp   = lane & 3;
    const int wm   = wid >> 1;    // 0..3 -> rows wm*32
    const int wn   = wid & 1;     // 0..1 -> cols wn*64
    const int row0 = blockIdx.x * 128;

    const uint32_t arow_off = (uint32_t)((lane & 15) * PITCHB + ((lane >> 4) << 4));
    const uint32_t brow_off = (uint32_t)((((lane >> 4) << 3) + (lane & 7)) * PITCHB + (((lane >> 3) & 1) << 4));

    float acc[2][8][4];
#pragma unroll
    for (int mf = 0; mf < 2; mf++)
#pragma unroll
        for (int nf = 0; nf < 8; nf++)
#pragma unroll
            for (int q = 0; q < 4; q++) acc[mf][nf][q] = 0.f;

    auto issue_chunk = [&](int c, uint32_t bufoff) {
        const uint16_t* Ah_g = (c < 2) ? Sh : g_mh;
        const uint16_t* Al_g = (c < 2) ? Sl : g_ml;
        const int kc = (c & 1) * 64;
        const int k0 = c * 64;
#pragma unroll
        for (int i = 0; i < 8; i++) {
            int idx = tid + i * 256;
            int mat = idx >> 10;
            int e   = idx & 1023;
            int r   = e >> 3;
            int c16 = e & 7;
            int gr  = row0 + r;
            int grs = (gr < NN) ? gr : 0;
            const uint16_t* srcp = (mat ? Al_g : Ah_g) + (size_t)grs * D + kc + c16 * 8;
            uint32_t dst = sbase + bufoff + (mat ? MATB : 0) + r * PITCHB + c16 * 16;
            cp16(dst, srcp, (gr < NN) ? 16u : 0u);
        }
#pragma unroll
        for (int i = 0; i < 8; i++) {
            int idx = tid + i * 256;
            int mat = idx >> 10;
            int e   = idx & 1023;
            int j   = e >> 3;
            int c16 = e & 7;
            const uint16_t* srcp = (mat ? WTl : WTh) + (size_t)j * 256 + k0 + c16 * 8;
            uint32_t dst = sbase + bufoff + (mat ? 3 * MATB : 2 * MATB) + j * PITCHB + c16 * 16;
            cp16(dst, srcp, 16u);
        }
    };

    issue_chunk(0, 0);
    asm volatile("cp.async.commit_group;" ::: "memory");

#pragma unroll
    for (int chunk = 0; chunk < 4; chunk++) {
        const uint32_t bufoff = (chunk & 1) * STAGEB;
        if (chunk < 3) {
            issue_chunk(chunk + 1, ((chunk + 1) & 1) * STAGEB);
            asm volatile("cp.async.commit_group;" ::: "memory");
            asm volatile("cp.async.wait_group 1;" ::: "memory");
        } else {
            asm volatile("cp.async.wait_group 0;" ::: "memory");
        }
        __syncthreads();

        const uint32_t aBaseH = sbase + bufoff + (wm * 32) * PITCHB + arow_off;
        const uint32_t aBaseL = aBaseH + MATB;
        const uint32_t bBaseH = sbase + bufoff + 2 * MATB + (wn * 64) * PITCHB + brow_off;
        const uint32_t bBaseL = bBaseH + MATB;

#pragma unroll
        for (int ks = 0; ks < 64; ks += 16) {
            // load ALL fragments for this k-step
            uint32_t ah[2][4], al[2][4];
            uint32_t bh[4][4], bl[4][4];
#pragma unroll
            for (int mf = 0; mf < 2; mf++) {
                ldsm_x4(ah[mf], aBaseH + mf * (16 * PITCHB) + ks * 2);
                ldsm_x4(al[mf], aBaseL + mf * (16 * PITCHB) + ks * 2);
            }
#pragma unroll
            for (int np = 0; np < 4; np++) {
                ldsm_x4(bh[np], bBaseH + np * (16 * PITCHB) + ks * 2);
                ldsm_x4(bl[np], bBaseL + np * (16 * PITCHB) + ks * 2);
            }
            // pass 1: Ah * Bh  (16 HMMAs, all accumulators once)
#pragma unroll
            for (int np = 0; np < 4; np++) {
#pragma unroll
                for (int mf = 0; mf < 2; mf++) {
                    mma_bf16(acc[mf][np * 2 + 0], ah[mf], bh[np][0], bh[np][1]);
                    mma_bf16(acc[mf][np * 2 + 1], ah[mf], bh[np][2], bh[np][3]);
                }
            }
            // pass 2: Al * Bh
#pragma unroll
            for (int np = 0; np < 4; np++) {
#pragma unroll
                for (int mf = 0; mf < 2; mf++) {
                    mma_bf16(acc[mf][np * 2 + 0], al[mf], bh[np][0], bh[np][1]);
                    mma_bf16(acc[mf][np * 2 + 1], al[mf], bh[np][2], bh[np][3]);
                }
            }
            // pass 3: Ah * Bl
#pragma unroll
            for (int np = 0; np < 4; np++) {
#pragma unroll
                for (int mf = 0; mf < 2; mf++) {
                    mma_bf16(acc[mf][np * 2 + 0], ah[mf], bl[np][0], bl[np][1]);
                    mma_bf16(acc[mf][np * 2 + 1], ah[mf], bl[np][2], bl[np][3]);
                }
            }
        }
        __syncthreads();
    }

    // epilogue
#pragma unroll
    for (int mf = 0; mf < 2; mf++) {
#pragma unroll
        for (int nf = 0; nf < 8; nf++) {
            int c = wn * 64 + nf * 8 + qp * 2;
            int r = row0 + wm * 32 + mf * 16 + grp;
            float bx = bias[c], by = bias[c + 1];
            float v00 = acc[mf][nf][0] + bx, v01 = acc[mf][nf][1] + by;
            float v10 = acc[mf][nf][2] + bx, v11 = acc[mf][nf][3] + by;
            if (RELU) {
                v00 = fmaxf(v00, 0.f); v01 = fmaxf(v01, 0.f);
                v10 = fmaxf(v10, 0.f); v11 = fmaxf(v11, 0.f);
            }
            if (SPLIT) {
                uint16_t h00 = bf_hi(v00), h01 = bf_hi(v01), h10 = bf_hi(v10), h11 = bf_hi(v11);
                uint16_t l00 = bf_hi(v00 - bf_f(h00)), l01 = bf_hi(v01 - bf_f(h01));
                uint16_t l10 = bf_hi(v10 - bf_f(h10)), l11 = bf_hi(v11 - bf_f(h11));
                if (r < NN) {
                    *(uint32_t*)(outH + (size_t)r * D + c) = (uint32_t)h00 | ((uint32_t)h01 << 16);
                    *(uint32_t*)(outL + (size_t)r * D + c) = (uint32_t)l00 | ((uint32_t)l01 << 16);
                }
                if (r + 8 < NN) {
                    *(uint32_t*)(outH + (size_t)(r + 8) * D + c) = (uint32_t)h10 | ((uint32_t)h11 << 16);
                    *(uint32_t*)(outL + (size_t)(r + 8) * D + c) = (uint32_t)l10 | ((uint32_t)l11 << 16);
                }
            } else {
                if (r < NN)     { float2 v = make_float2(v00, v01); *(float2*)(outF + (size_t)r * D + c) = v; }
                if (r + 8 < NN) { float2 v = make_float2(v10, v11); *(float2*)(outF + (size_t)(r + 8) * D + c) = v; }
            }
        }
    }
}

// ---------------- launch ----------------
extern "C" void kernel_launch(void* const* d_in, const int* in_sizes, int n_in,
                              void* d_out, int out_size) {
    const float* x   = (const float*)d_in[0];
    const float* W1s = (const float*)d_in[1];
    const float* W1n = (const float*)d_in[2];
    const float* b1  = (const float*)d_in[3];
    const float* W2s = (const float*)d_in[4];
    const float* W2n = (const float*)d_in[5];
    const float* b2  = (const float*)d_in[6];
    const int*   src = (const int*)d_in[7];
    const int*   dst = (const int*)d_in[8];
    float* out = (float*)d_out;

    uint16_t *xh, *xl, *hh, *hl, *wt1h, *wt1l, *wt2h, *wt2l;
    cudaGetSymbolAddress((void**)&xh, g_Xh);
    cudaGetSymbolAddress((void**)&xl, g_Xl);
    cudaGetSymbolAddress((void**)&hh, g_hh);
    cudaGetSymbolAddress((void**)&hl, g_hl);
    cudaGetSymbolAddress((void**)&wt1h, g_WT1h);
    cudaGetSymbolAddress((void**)&wt1l, g_WT1l);
    cudaGetSymbolAddress((void**)&wt2h, g_WT2h);
    cudaGetSymbolAddress((void**)&wt2l, g_WT2l);

    cudaFuncSetAttribute(gemm_async_kernel<true, true>,   cudaFuncAttributeMaxDynamicSharedMemorySize, SM_BYTES);
    cudaFuncSetAttribute(gemm_async_kernel<false, false>, cudaFuncAttributeMaxDynamicSharedMemorySize, SM_BYTES);

    const int gemmGrid = (NN + 127) / 128;   // 782

    init_kernel<<<(NN * D / 4 + 255) / 256, 256>>>(x, W1s, W1n, W2s, W2n);
    fill_kernel<<<(EE + 255) / 256, 256>>>(src, dst);

    // layer 1
    agg_f32_kernel<<<(NN * 32 + 255) / 256, 256>>>(x);
    gemm_async_kernel<true, true><<<gemmGrid, 256, SM_BYTES>>>(xh, xl, wt1h, wt1l, b1, nullptr, hh, hl);

    // layer 2
    agg_bf_kernel<<<(NN * 32 + 255) / 256, 256>>>();
    gemm_async_kernel<false, false><<<gemmGrid, 256, SM_BYTES>>>(hh, hl, wt2h, wt2l, b2, out, nullptr, nullptr);
}